// round 1
// baseline (speedup 1.0000x reference)
#include <cuda_runtime.h>
#include <cstdint>

#define T_DIM 1024
#define B_DIM 32
#define D_DIM 512
#define C_DIM 1024
#define BLANK 0

// Output packing (floats): [out (T*B*D)] [out_padding (B*T)] [gloss (B*T)] [new_len (B)]
#define OFF_PAD   ((size_t)T_DIM * B_DIM * D_DIM)
#define OFF_GLOSS (OFF_PAD + (size_t)B_DIM * T_DIM)
#define OFF_LEN   (OFF_GLOSS + (size_t)B_DIM * T_DIM)

// Scratch (device globals; no allocations allowed)
__device__ int g_pred[B_DIM * T_DIM];       // pred per (b,t), blank-forced by padding
__device__ int g_comp_t[B_DIM * T_DIM];     // original frame index of j-th non-blank frame
__device__ int g_run_start[B_DIM * T_DIM];  // compacted index of first frame of run n
__device__ int g_run_cnt[B_DIM * T_DIM];    // frames in run n
__device__ int g_new_len[B_DIM];            // number of runs per batch

// ---------------------------------------------------------------------------
// K1: argmax over C for each (t,b) row of logit [T,B,C]. Warp per row.
// ---------------------------------------------------------------------------
__global__ void argmax_kernel(const float* __restrict__ logit,
                              const unsigned char* __restrict__ padding) {
    int warp = (blockIdx.x * blockDim.x + threadIdx.x) >> 5;
    int lane = threadIdx.x & 31;
    if (warp >= T_DIM * B_DIM) return;
    int t = warp / B_DIM;
    int b = warp % B_DIM;

    const float4* row = reinterpret_cast<const float4*>(logit + (size_t)warp * C_DIM);

    float best = -3.402823466e+38f;
    int bi = 0;
    #pragma unroll
    for (int k = 0; k < C_DIM / (32 * 4); k++) {
        int i4 = lane + 32 * k;
        float4 v = row[i4];
        int base = i4 * 4;
        if (v.x > best) { best = v.x; bi = base; }
        if (v.y > best) { best = v.y; bi = base + 1; }
        if (v.z > best) { best = v.z; bi = base + 2; }
        if (v.w > best) { best = v.w; bi = base + 3; }
    }
    // warp reduce: strictly-greater wins; on exact tie, lower index wins
    #pragma unroll
    for (int off = 16; off; off >>= 1) {
        float ov = __shfl_down_sync(0xFFFFFFFFu, best, off);
        int   oi = __shfl_down_sync(0xFFFFFFFFu, bi, off);
        if (ov > best || (ov == best && oi < bi)) { best = ov; bi = oi; }
    }
    if (lane == 0) {
        int p = padding[b * T_DIM + t] ? BLANK : bi;
        g_pred[b * T_DIM + t] = p;
    }
}

// ---------------------------------------------------------------------------
// K2: per-batch compaction + run-length grouping. One block of T threads per b.
// Emits run metadata + the three small outputs (padding, gloss, new_len).
// ---------------------------------------------------------------------------
__global__ void rle_kernel(float* __restrict__ out) {
    int b = blockIdx.x;
    int t = threadIdx.x;  // 0..1023

    __shared__ int s_scan[T_DIM];
    __shared__ int s_cp[T_DIM];
    __shared__ int s_start[T_DIM];
    __shared__ int s_runstart[T_DIM];

    int p = g_pred[b * T_DIM + t];
    int m = (p != BLANK) ? 1 : 0;

    // inclusive scan of mask -> compaction destination
    s_scan[t] = m;
    __syncthreads();
    #pragma unroll
    for (int off = 1; off < T_DIM; off <<= 1) {
        int add = (t >= off) ? s_scan[t - off] : 0;
        __syncthreads();
        s_scan[t] += add;
        __syncthreads();
    }
    int dest = s_scan[t] - 1;
    int nb_total = s_scan[T_DIM - 1];
    __syncthreads();

    // scatter compacted predictions + original frame indices
    s_cp[t] = -1;
    __syncthreads();
    if (m) {
        s_cp[dest] = p;
        g_comp_t[b * T_DIM + dest] = t;
    }
    __syncthreads();

    // run starts on compacted stream
    int cj = s_cp[t];
    int startj = (cj >= 0) && (t == 0 || s_cp[t - 1] != cj);
    s_start[t] = startj;
    s_scan[t] = startj;
    __syncthreads();
    #pragma unroll
    for (int off = 1; off < T_DIM; off <<= 1) {
        int add = (t >= off) ? s_scan[t - off] : 0;
        __syncthreads();
        s_scan[t] += add;
        __syncthreads();
    }
    int seg = s_scan[t] - 1;
    int new_len = s_scan[T_DIM - 1];
    __syncthreads();

    if (startj) s_runstart[seg] = t;
    __syncthreads();

    // per-run outputs (thread t = output position n)
    int n = t;
    float gloss = -1.0f;
    if (n < new_len) {
        int rs = s_runstart[n];
        int re = (n + 1 < new_len) ? s_runstart[n + 1] : nb_total;
        g_run_start[b * T_DIM + n] = rs;
        g_run_cnt[b * T_DIM + n] = re - rs;
        gloss = (float)s_cp[rs];
    }
    out[OFF_GLOSS + (size_t)b * T_DIM + n] = gloss;
    out[OFF_PAD   + (size_t)b * T_DIM + n] = (n >= new_len) ? 1.0f : 0.0f;
    if (t == 0) {
        g_new_len[b] = new_len;
        out[OFF_LEN + b] = (float)new_len;
    }
}

// ---------------------------------------------------------------------------
// K3: out[n,b,:] = mean of rep[t,b,:] over frames of run n; zeros if n>=len.
// Block per (n,b); 128 threads x float4 cover D=512.
// ---------------------------------------------------------------------------
__global__ void gather_avg_kernel(const float* __restrict__ rep,
                                  float* __restrict__ out) {
    int n = blockIdx.x;
    int b = blockIdx.y;
    int d4 = threadIdx.x;  // 0..127

    float4* orow = reinterpret_cast<float4*>(out + ((size_t)n * B_DIM + b) * D_DIM);
    int len = g_new_len[b];
    if (n >= len) {
        orow[d4] = make_float4(0.f, 0.f, 0.f, 0.f);
        return;
    }
    int rs  = g_run_start[b * T_DIM + n];
    int cnt = g_run_cnt[b * T_DIM + n];

    float4 acc = make_float4(0.f, 0.f, 0.f, 0.f);
    for (int k = 0; k < cnt; k++) {
        int t = g_comp_t[b * T_DIM + rs + k];
        const float4* rrow =
            reinterpret_cast<const float4*>(rep + ((size_t)t * B_DIM + b) * D_DIM);
        float4 v = rrow[d4];
        acc.x += v.x; acc.y += v.y; acc.z += v.z; acc.w += v.w;
    }
    float inv = 1.0f / (float)cnt;
    acc.x *= inv; acc.y *= inv; acc.z *= inv; acc.w *= inv;
    orow[d4] = acc;
}

extern "C" void kernel_launch(void* const* d_in, const int* in_sizes, int n_in,
                              void* d_out, int out_size) {
    const float* rep = (const float*)d_in[0];          // [T,B,D] f32
    const float* logit = (const float*)d_in[1];        // [T,B,C] f32
    const unsigned char* padding = (const unsigned char*)d_in[2];  // [B,T] bool
    float* out = (float*)d_out;

    // K1: 32768 rows, warp per row, 256 threads/block -> 8 rows/block
    argmax_kernel<<<(T_DIM * B_DIM) / 8, 256>>>(logit, padding);

    // K2: one block per batch
    rle_kernel<<<B_DIM, T_DIM>>>(out);

    // K3: block per (n,b)
    dim3 grid3(T_DIM, B_DIM);
    gather_avg_kernel<<<grid3, 128>>>(rep, out);
}

// round 3
// speedup vs baseline: 1.0264x; 1.0264x over previous
#include <cuda_runtime.h>
#include <cstdint>

#define T_DIM 1024
#define B_DIM 32
#define D_DIM 512
#define C_DIM 1024
#define BLANK 0

// Output packing (floats): [out (T*B*D)] [out_padding (B*T)] [gloss (B*T)] [new_len (B)]
#define OFF_PAD   ((size_t)T_DIM * B_DIM * D_DIM)
#define OFF_GLOSS (OFF_PAD + (size_t)B_DIM * T_DIM)
#define OFF_LEN   (OFF_GLOSS + (size_t)B_DIM * T_DIM)

// Scratch (device globals; no allocations allowed)
__device__ int g_pred[B_DIM * T_DIM];       // pred per (b,t), blank-forced by padding
__device__ int g_comp_t[B_DIM * T_DIM];     // original frame index of j-th non-blank frame
__device__ int g_run_start[B_DIM * T_DIM];  // compacted index of first frame of run n
__device__ int g_run_cnt[B_DIM * T_DIM];    // frames in run n
__device__ int g_new_len[B_DIM];            // number of runs per batch

// ---------------------------------------------------------------------------
// K1: argmax over C for each (t,b) row of logit [T,B,C]. Warp per row.
// ---------------------------------------------------------------------------
__global__ void argmax_kernel(const float* __restrict__ logit,
                              const unsigned char* __restrict__ padding) {
    int warp = (blockIdx.x * blockDim.x + threadIdx.x) >> 5;
    int lane = threadIdx.x & 31;
    if (warp >= T_DIM * B_DIM) return;
    int t = warp / B_DIM;
    int b = warp % B_DIM;

    const float4* row = reinterpret_cast<const float4*>(logit + (size_t)warp * C_DIM);

    float best = -3.402823466e+38f;
    int bi = 0;
    #pragma unroll
    for (int k = 0; k < C_DIM / (32 * 4); k++) {
        int i4 = lane + 32 * k;
        float4 v = row[i4];
        int base = i4 * 4;
        if (v.x > best) { best = v.x; bi = base; }
        if (v.y > best) { best = v.y; bi = base + 1; }
        if (v.z > best) { best = v.z; bi = base + 2; }
        if (v.w > best) { best = v.w; bi = base + 3; }
    }
    // warp reduce: strictly-greater wins; on exact tie, lower index wins
    #pragma unroll
    for (int off = 16; off; off >>= 1) {
        float ov = __shfl_down_sync(0xFFFFFFFFu, best, off);
        int   oi = __shfl_down_sync(0xFFFFFFFFu, bi, off);
        if (ov > best || (ov == best && oi < bi)) { best = ov; bi = oi; }
    }
    if (lane == 0) {
        int p = padding[b * T_DIM + t] ? BLANK : bi;
        g_pred[b * T_DIM + t] = p;
    }
}

// ---------------------------------------------------------------------------
// K2: per-batch compaction + run-length grouping. One block of T threads per b.
// Two-level scans (warp shfl + single cross-warp scan) -> only 6 barriers.
// ---------------------------------------------------------------------------
__global__ void rle_kernel(float* __restrict__ out) {
    int b = blockIdx.x;
    int t = threadIdx.x;           // 0..1023
    int lane = t & 31;
    int w = t >> 5;                // warp 0..31

    __shared__ int s_cp[T_DIM];
    __shared__ int s_runstart[T_DIM];
    __shared__ int s_w[32];

    int p = g_pred[b * T_DIM + t];
    int m = (p != BLANK) ? 1 : 0;

    // ---- scan 1: compaction destinations ----
    int v = m;
    #pragma unroll
    for (int o = 1; o < 32; o <<= 1) {
        int x = __shfl_up_sync(0xFFFFFFFFu, v, o);
        if (lane >= o) v += x;
    }
    if (lane == 31) s_w[w] = v;
    s_cp[t] = -1;                  // init compacted stream (pre-barrier)
    __syncthreads();               // (1)
    if (w == 0) {
        int x = s_w[lane];
        #pragma unroll
        for (int o = 1; o < 32; o <<= 1) {
            int y = __shfl_up_sync(0xFFFFFFFFu, x, o);
            if (lane >= o) x += y;
        }
        s_w[lane] = x;
    }
    __syncthreads();               // (2)
    int incl = v + (w ? s_w[w - 1] : 0);
    int nb_total = s_w[31];
    int dest = incl - 1;
    __syncthreads();               // (3) all reads of s_w / s_cp-init done before scatter

    if (m) {
        s_cp[dest] = p;
        g_comp_t[b * T_DIM + dest] = t;
    }
    __syncthreads();               // (4)

    // ---- scan 2: run starts on compacted stream ----
    int cj = s_cp[t];
    int prev = (t == 0) ? -2 : s_cp[t - 1];
    int st = (cj >= 0 && cj != prev) ? 1 : 0;

    v = st;
    #pragma unroll
    for (int o = 1; o < 32; o <<= 1) {
        int x = __shfl_up_sync(0xFFFFFFFFu, v, o);
        if (lane >= o) v += x;
    }
    if (lane == 31) s_w[w] = v;
    __syncthreads();               // (5)
    if (w == 0) {
        int x = s_w[lane];
        #pragma unroll
        for (int o = 1; o < 32; o <<= 1) {
            int y = __shfl_up_sync(0xFFFFFFFFu, x, o);
            if (lane >= o) x += y;
        }
        s_w[lane] = x;
    }
    __syncthreads();               // (6)
    int seg = v + (w ? s_w[w - 1] : 0) - 1;
    int new_len = s_w[31];

    if (st) s_runstart[seg] = t;
    __syncthreads();               // (7)

    // ---- per-run outputs (thread t = output position n) ----
    int n = t;
    float gloss = -1.0f;
    if (n < new_len) {
        int rs = s_runstart[n];
        int re = (n + 1 < new_len) ? s_runstart[n + 1] : nb_total;
        g_run_start[b * T_DIM + n] = rs;
        g_run_cnt[b * T_DIM + n] = re - rs;
        gloss = (float)s_cp[rs];
    }
    out[OFF_GLOSS + (size_t)b * T_DIM + n] = gloss;
    out[OFF_PAD   + (size_t)b * T_DIM + n] = (n >= new_len) ? 1.0f : 0.0f;
    if (t == 0) {
        g_new_len[b] = new_len;
        out[OFF_LEN + b] = (float)new_len;
    }
}

// ---------------------------------------------------------------------------
// K3: out[n,b,:] = mean of rep[t,b,:] over frames of run n; zeros if n>=len.
// Block per (n,b); 128 threads x float4 cover D=512.
// ---------------------------------------------------------------------------
__global__ void gather_avg_kernel(const float* __restrict__ rep,
                                  float* __restrict__ out) {
    int n = blockIdx.x;
    int b = blockIdx.y;
    int d4 = threadIdx.x;  // 0..127

    float4* orow = reinterpret_cast<float4*>(out + ((size_t)n * B_DIM + b) * D_DIM);
    int len = g_new_len[b];
    if (n >= len) {
        orow[d4] = make_float4(0.f, 0.f, 0.f, 0.f);
        return;
    }
    int rs  = g_run_start[b * T_DIM + n];
    int cnt = g_run_cnt[b * T_DIM + n];

    float4 acc = make_float4(0.f, 0.f, 0.f, 0.f);
    for (int k = 0; k < cnt; k++) {
        int t = g_comp_t[b * T_DIM + rs + k];
        const float4* rrow =
            reinterpret_cast<const float4*>(rep + ((size_t)t * B_DIM + b) * D_DIM);
        float4 v = rrow[d4];
        acc.x += v.x; acc.y += v.y; acc.z += v.z; acc.w += v.w;
    }
    float inv = 1.0f / (float)cnt;
    acc.x *= inv; acc.y *= inv; acc.z *= inv; acc.w *= inv;
    orow[d4] = acc;
}

extern "C" void kernel_launch(void* const* d_in, const int* in_sizes, int n_in,
                              void* d_out, int out_size) {
    const float* rep = (const float*)d_in[0];          // [T,B,D] f32
    const float* logit = (const float*)d_in[1];        // [T,B,C] f32
    const unsigned char* padding = (const unsigned char*)d_in[2];  // [B,T] bool
    float* out = (float*)d_out;

    // K1: 32768 rows, warp per row, 256 threads/block -> 8 rows/block
    argmax_kernel<<<(T_DIM * B_DIM) / 8, 256>>>(logit, padding);

    // K2: one block per batch
    rle_kernel<<<B_DIM, T_DIM>>>(out);

    // K3: block per (n,b)
    dim3 grid3(T_DIM, B_DIM);
    gather_avg_kernel<<<grid3, 128>>>(rep, out);
}